// round 14
// baseline (speedup 1.0000x reference)
#include <cuda_runtime.h>
#include <cuda_fp16.h>
#include <cstdint>

#define NCELL 65536
#define TST   365
#define CPB   64
#define NBLK  (NCELL / CPB)

// smem byte offsets
#define H16   0        // h f16 tile: 2 bufs x 64 rows x 144B   = 18432
#define X16   18432    // x f16 tile: 2 bufs x 64 rows x 16B    =  2048
#define PTB   20480    // p,t fp32:   2 bufs x 64 x float2      =  1024
#define YPT   21504    // y partials: 2 bufs x 8 x 64 f32       =  4096
#define SMB   25600

typedef unsigned int u32;
typedef unsigned short u16;

static __device__ __forceinline__ u32 s2u(const void* p) {
    u32 a;
    asm("{ .reg .u64 t; cvta.to.shared.u64 t, %1; cvt.u32.u64 %0, t; }"
        : "=r"(a) : "l"(p));
    return a;
}
static __device__ __forceinline__ u16 f2h(float f) {
    return __half_as_ushort(__float2half(f));
}
static __device__ __forceinline__ u32 pk(u16 a, u16 b) {
    return (u32)a | ((u32)b << 16);
}
static __device__ __forceinline__ float tanha(float x) {
    float r;
    asm("tanh.approx.f32 %0, %1;" : "=f"(r) : "f"(x));
    return r;
}
// packed sigmoid of an f16x2 pre-activation pair (from f16-accum MMA output)
static __device__ __forceinline__ float2 sigm2p(u32 x2) {
    u32 s, th;
    asm("mul.f16x2 %0, %1, %2;" : "=r"(s) : "r"(x2), "r"(0x38003800u));  // *0.5
    asm("tanh.approx.f16x2 %0, %1;" : "=r"(th) : "r"(s));
    __half2 h2 = *reinterpret_cast<__half2*>(&th);
    float2 f = __half22float2(h2);
    return make_float2(fmaf(f.x, 0.5f, 0.5f), fmaf(f.y, 0.5f, 0.5f));
}

#define LDSM4(R, ad) \
    asm volatile("ldmatrix.sync.aligned.m8n8.x4.shared.b16 {%0,%1,%2,%3}, [%4];" \
        : "=r"((R)[0]), "=r"((R)[1]), "=r"((R)[2]), "=r"((R)[3]) : "r"(ad) : "memory")
#define LDSM2(R, ad) \
    asm volatile("ldmatrix.sync.aligned.m8n8.x2.shared.b16 {%0,%1}, [%2];" \
        : "=r"((R)[0]), "=r"((R)[1]) : "r"(ad) : "memory")
// f32-accum (candidate gate)
#define HMMA16F(D, A, B0, B1) \
    asm("mma.sync.aligned.m16n8k16.row.col.f32.f16.f16.f32 " \
        "{%0,%1,%2,%3}, {%4,%5,%6,%7}, {%8,%9}, {%0,%1,%2,%3};" \
        : "+f"((D)[0]), "+f"((D)[1]), "+f"((D)[2]), "+f"((D)[3]) \
        : "r"((A)[0]), "r"((A)[1]), "r"((A)[2]), "r"((A)[3]), "r"(B0), "r"(B1))
#define HMMA8F(D, A, B0) \
    asm("mma.sync.aligned.m16n8k8.row.col.f32.f16.f16.f32 " \
        "{%0,%1,%2,%3}, {%4,%5}, {%6}, {%0,%1,%2,%3};" \
        : "+f"((D)[0]), "+f"((D)[1]), "+f"((D)[2]), "+f"((D)[3]) \
        : "r"((A)[0]), "r"((A)[1]), "r"(B0))
// f16-accum (r,z gates) — D/C are 2 packed f16x2 regs
#define HMMA16H(D, A, B0, B1) \
    asm("mma.sync.aligned.m16n8k16.row.col.f16.f16.f16.f16 " \
        "{%0,%1}, {%2,%3,%4,%5}, {%6,%7}, {%0,%1};" \
        : "+r"((D)[0]), "+r"((D)[1]) \
        : "r"((A)[0]), "r"((A)[1]), "r"((A)[2]), "r"((A)[3]), "r"(B0), "r"(B1))
#define HMMA8H(D, A, B0) \
    asm("mma.sync.aligned.m16n8k8.row.col.f16.f16.f16.f16 " \
        "{%0,%1}, {%2,%3}, {%4}, {%0,%1};" \
        : "+r"((D)[0]), "+r"((D)[1]) \
        : "r"((A)[0]), "r"((A)[1]), "r"(B0))

__global__ void __launch_bounds__(256, 2)
gru_f16_kernel(const float* __restrict__ precip, const float* __restrict__ temp,
               const float* __restrict__ w_ih, const float* __restrict__ w_hh,
               const float* __restrict__ bias, const float* __restrict__ bias_n,
               const float* __restrict__ out_w, const float* __restrict__ out_b,
               const float* __restrict__ init_h, float* __restrict__ out) {
    extern __shared__ char sm[];
    const u32 sb = s2u(sm);
    u16*  h16  = (u16*)(sm + H16);           // two 4608-u16 buffers
    float2* ptb = (float2*)(sm + PTB);
    float* ybuf = (float*)(sm + YPT);

    const int tid  = threadIdx.x;
    const int wid  = tid >> 5;
    const int lane = tid & 31;
    const int g    = lane >> 2;
    const int c4   = lane & 3;
    const int k0   = 8 * wid + 2 * c4;
    const int cellbase = blockIdx.x * CPB;
    const int scell = wid * 8 + (lane & 7);  // staging cell (lane<8 active)

    // ---- W_hh register fragments (rounded f16) ----
    u32 Bh[3][4][2];
#pragma unroll
    for (int grp = 0; grp < 3; ++grp) {
        const float* wr = w_hh + (grp * 64 + 8 * wid + g) * 64;
#pragma unroll
        for (int c = 0; c < 4; ++c)
#pragma unroll
            for (int rr = 0; rr < 2; ++rr) {
                int kk = c * 16 + rr * 8 + 2 * c4;
                Bh[grp][c][rr] = pk(f2h(wr[kk]), f2h(wr[kk + 1]));
            }
    }
    // ---- x-chunk B frags: r,z carry (w_p,w_t | bias); n carries (0 | bias_n) ----
    u32 Bx[3];
#pragma unroll
    for (int grp = 0; grp < 2; ++grp) {
        int gate = grp * 64 + 8 * wid + g;
        u32 v = 0;
        if (c4 == 0)      v = pk(f2h(w_ih[gate * 2]), f2h(w_ih[gate * 2 + 1]));
        else if (c4 == 1) v = pk(f2h(bias[gate]), 0);
        Bx[grp] = v;
    }
    {
        u32 v = 0;
        if (c4 == 1) v = pk(f2h(bias_n[8 * wid + g]), 0);
        Bx[2] = v;
    }
    // ---- exact scalars for candidate gate + output ----
    const float wp0 = w_ih[(128 + k0) * 2],     wt0 = w_ih[(128 + k0) * 2 + 1];
    const float wp1 = w_ih[(128 + k0 + 1) * 2], wt1 = w_ih[(128 + k0 + 1) * 2 + 1];
    const float bb0 = bias[128 + k0], bb1 = bias[128 + k0 + 1];
    const float ow0 = out_w[k0],      ow1 = out_w[k0 + 1];
    const float ob  = out_b[0];

    // ---- h state: fp32 in regs ----
    float hreg[16];
#pragma unroll
    for (int u = 0; u < 16; ++u) hreg[u] = init_h[k0 + (u & 1)];
    for (int idx = tid; idx < 64 * 64; idx += 256)
        h16[(idx >> 6) * 72 + (idx & 63)] = f2h(init_h[idx & 63]);
    // x buf 0 (t=0) + pt buf 0; prefetch t=1 (distributed: lane<8 per warp)
    float pv = 0.f, tv = 0.f;
    if (lane < 8) {
        float p0 = precip[cellbase + scell], t0 = temp[cellbase + scell];
        *(uint4*)(sm + X16 + scell * 16) =
            make_uint4(pk(f2h(p0), f2h(t0)), pk(0x3C00, 0), 0, 0);  // 1.0h
        ptb[scell] = make_float2(p0, t0);
        pv = precip[NCELL + cellbase + scell];
        tv = temp[NCELL + cellbase + scell];
    }
    __syncthreads();

    const u32 ah_lm = sb + H16 + (u32)((lane & 15) * 144 + (lane >> 4) * 16);
    const u32 ax_lm = sb + X16 + (u32)((lane & 15) * 16);

    for (int t = 0; t < TST; ++t) {
        const int pr = t & 1, nx = (t + 1) & 1;

        // ---- staging (all warps, lane<8): x(t+1), pt(t+1), y(t-1), prefetch ----
        if (lane < 8) {
            *(uint4*)(sm + X16 + nx * 1024 + scell * 16) =
                make_uint4(pk(f2h(pv), f2h(tv)), pk(0x3C00, 0), 0, 0);
            ptb[nx * CPB + scell] = make_float2(pv, tv);
            int tn = (t + 2 < TST) ? t + 2 : TST - 1;
            pv = precip[tn * NCELL + cellbase + scell];
            tv = temp[tn * NCELL + cellbase + scell];
            if (t > 0) {
                float y = ob;
                const float* yb = ybuf + nx * 512;   // (t-1)&1 == nx
#pragma unroll
                for (int w = 0; w < 8; ++w) y += yb[w * CPB + scell];
                out[(t - 1) * NCELL + cellbase + scell] = y;
            }
        }

        // ---- MMA: reads hbuf[pr], xbuf[pr] ----
        u32  drz[4][2][2];   // f16x2 accum: [mt][r|z][hf]
        float dn[4][4];      // f32 accum:  [mt][q]
#pragma unroll
        for (int mt = 0; mt < 4; ++mt) {
            drz[mt][0][0] = drz[mt][0][1] = 0u;
            drz[mt][1][0] = drz[mt][1][1] = 0u;
            dn[mt][0] = dn[mt][1] = dn[mt][2] = dn[mt][3] = 0.f;
        }
        const u32 ah_b = ah_lm + (u32)(pr * 9216);
        const u32 ax_b = ax_lm + (u32)(pr * 1024);
#pragma unroll
        for (int c = 0; c < 4; ++c) {
            u32 a[4][4];
#pragma unroll
            for (int mt = 0; mt < 4; ++mt)
                LDSM4(a[mt], ah_b + mt * 2304 + c * 32);
#pragma unroll
            for (int mt = 0; mt < 4; ++mt) {
                HMMA16H(drz[mt][0], a[mt], Bh[0][c][0], Bh[0][c][1]);
                HMMA16H(drz[mt][1], a[mt], Bh[1][c][0], Bh[1][c][1]);
                HMMA16F(dn[mt],     a[mt], Bh[2][c][0], Bh[2][c][1]);
            }
        }
#pragma unroll
        for (int mt = 0; mt < 4; ++mt) {
            u32 ax[2];
            LDSM2(ax, ax_b + mt * 256);
            HMMA8H(drz[mt][0], ax, Bx[0]);
            HMMA8H(drz[mt][1], ax, Bx[1]);
            HMMA8F(dn[mt],     ax, Bx[2]);     // bias_n into candidate pre-act
        }

        // ---- epilogue: writes hbuf[nx], ybuf[pr] ----
        u16* h16w = h16 + nx * 4608;
        const float2* ptc = ptb + pr * CPB;
        float* yb = ybuf + pr * 512;
#pragma unroll
        for (int mt = 0; mt < 4; ++mt) {
#pragma unroll
            for (int hf = 0; hf < 2; ++hf) {
                const int cell = mt * 16 + g + hf * 8;
                const int u = mt * 4 + hf * 2;
                float2 xv = ptc[cell];
                float2 rr = sigm2p(drz[mt][0][hf]);
                float2 zz = sigm2p(drz[mt][1][hf]);
                float Dn0 = dn[mt][2 * hf], Dn1 = dn[mt][2 * hf + 1];
                float ig0 = fmaf(wp0, xv.x, fmaf(wt0, xv.y, bb0));
                float ig1 = fmaf(wp1, xv.x, fmaf(wt1, xv.y, bb1));
                float n0 = tanha(fmaf(rr.x, Dn0, ig0));
                float n1 = tanha(fmaf(rr.y, Dn1, ig1));
                float h0 = fmaf(zz.x, hreg[u] - n0, n0);
                float h1 = fmaf(zz.y, hreg[u + 1] - n1, n1);
                hreg[u] = h0; hreg[u + 1] = h1;
                *(u32*)&h16w[cell * 72 + k0] = pk(f2h(h0), f2h(h1));
                float yq = fmaf(ow0, h0, ow1 * h1);
                yq += __shfl_xor_sync(0xffffffffu, yq, 1);
                yq += __shfl_xor_sync(0xffffffffu, yq, 2);
                if (c4 == 0) yb[wid * CPB + cell] = yq;
            }
        }
        __syncthreads();   // single barrier per step
    }

    // trailing y reduce for t = TST-1 (distributed)
    if (lane < 8) {
        float y = ob;
        const float* yb = ybuf + ((TST - 1) & 1) * 512;
#pragma unroll
        for (int w = 0; w < 8; ++w) y += yb[w * CPB + scell];
        out[(TST - 1) * NCELL + cellbase + scell] = y;
    }

    // ---- final hidden state (exact fp32 from regs) ----
#pragma unroll
    for (int u = 0; u < 16; ++u) {
        int cell = (u >> 2) * 16 + g + ((u >> 1) & 1) * 8;
        int k = k0 + (u & 1);
        out[(long long)TST * NCELL + (long long)(cellbase + cell) * 64 + k] = hreg[u];
    }
}

extern "C" void kernel_launch(void* const* d_in, const int* in_sizes, int n_in,
                              void* d_out, int out_size) {
    const float* precip = (const float*)d_in[0];
    const float* temp   = (const float*)d_in[1];
    const float* w_ih   = (const float*)d_in[2];
    const float* w_hh   = (const float*)d_in[3];
    const float* bias   = (const float*)d_in[4];
    const float* bias_n = (const float*)d_in[5];
    const float* out_w  = (const float*)d_in[6];
    const float* out_b  = (const float*)d_in[7];
    const float* init_h = (const float*)d_in[8];
    float* out = (float*)d_out;

    gru_f16_kernel<<<NBLK, 256, SMB>>>(
        precip, temp, w_ih, w_hh, bias, bias_n, out_w, out_b, init_h, out);
}